// round 2
// baseline (speedup 1.0000x reference)
#include <cuda_runtime.h>
#include <math.h>

#define BATCH   32768
#define D_IN    512
#define D_DENSE 256
#define TSTEPS  16
#define FEAT    16
#define H1      128
#define H2      32
#define NCLS    10

// ---------------- scratch (static device globals; no allocation) ----------------
__device__ float g_act[BATCH * D_DENSE];          // dense1+bn+lrelu output, [B,256]
__device__ float g_h1[2][BATCH * H1];             // ping-pong hidden LSTM1
__device__ float g_c1[BATCH * H1];                // cell LSTM1 (in-place safe)
__device__ float g_h2[2][BATCH * H2];             // ping-pong hidden LSTM2
__device__ float g_c2[BATCH * H2];                // cell LSTM2
__device__ float g_Wc1[(FEAT + H1) * 4 * H1];     // [144,512] gate-interleaved [x|h] weights
__device__ float g_bc1[4 * H1];
__device__ float g_Wc2[(H1 + H2) * 4 * H2];       // [160,128]
__device__ float g_bc2[4 * H2];

// ---------------- init: zero initial states ----------------
__global__ void init_state_kernel() {
    int idx = blockIdx.x * blockDim.x + threadIdx.x;
    int stride = gridDim.x * blockDim.x;
    for (int i = idx; i < BATCH * H1; i += stride) { g_h1[0][i] = 0.f; g_c1[i] = 0.f; }
    for (int i = idx; i < BATCH * H2; i += stride) { g_h2[0][i] = 0.f; g_c2[i] = 0.f; }
}

// ---------------- repack LSTM weights: column n = 4*u + gate, rows = [x | h] ----------------
__global__ void repack_kernel(const float* __restrict__ Wx1, const float* __restrict__ Wh1,
                              const float* __restrict__ b1,
                              const float* __restrict__ Wx2, const float* __restrict__ Wh2,
                              const float* __restrict__ b2) {
    int idx = blockIdx.x * blockDim.x + threadIdx.x;
    int stride = gridDim.x * blockDim.x;
    // LSTM1: K=144, N=512
    for (int i = idx; i < (FEAT + H1) * 4 * H1; i += stride) {
        int k = i / (4 * H1), n = i % (4 * H1);
        int u = n >> 2, g = n & 3;
        int src = g * H1 + u;
        g_Wc1[i] = (k < FEAT) ? Wx1[k * 4 * H1 + src] : Wh1[(k - FEAT) * 4 * H1 + src];
    }
    for (int i = idx; i < 4 * H1; i += stride) {
        int u = i >> 2, g = i & 3;
        g_bc1[i] = b1[g * H1 + u];
    }
    // LSTM2: K=160, N=128
    for (int i = idx; i < (H1 + H2) * 4 * H2; i += stride) {
        int k = i / (4 * H2), n = i % (4 * H2);
        int u = n >> 2, g = n & 3;
        int src = g * H2 + u;
        g_Wc2[i] = (k < H1) ? Wx2[k * 4 * H2 + src] : Wh2[(k - H1) * 4 * H2 + src];
    }
    for (int i = idx; i < 4 * H2; i += stride) {
        int u = i >> 2, g = i & 3;
        g_bc2[i] = b2[g * H2 + u];
    }
}

// ---------------- Dense1 + BatchNorm + LeakyReLU ----------------
// C[B,256] = x[B,512] @ Wd1[512,256], then bn + leaky, write g_act.
__global__ __launch_bounds__(256) void dense1_kernel(
    const float* __restrict__ x, const float* __restrict__ Wd1, const float* __restrict__ bd1,
    const float* __restrict__ gamma, const float* __restrict__ beta,
    const float* __restrict__ mean, const float* __restrict__ var) {
    __shared__ float As[16][65];
    __shared__ float Bs[16][64];
    const int tid = threadIdx.x;
    const int tx = tid & 15, ty = tid >> 4;
    const int row0 = blockIdx.x * 64, n0 = blockIdx.y * 64;
    float acc[4][4] = {};
    for (int kc = 0; kc < D_IN / 16; kc++) {
        int kg0 = kc * 16;
#pragma unroll
        for (int i = 0; i < 4; i++) {
            int li = tid + i * 256;
            int k = li & 15, r = li >> 4;
            As[k][r] = x[(size_t)(row0 + r) * D_IN + kg0 + k];
        }
#pragma unroll
        for (int i = 0; i < 4; i++) {
            int li = tid + i * 256;
            int n = li & 63, k = li >> 6;
            Bs[k][n] = Wd1[(size_t)(kg0 + k) * D_DENSE + n0 + n];
        }
        __syncthreads();
#pragma unroll
        for (int k = 0; k < 16; k++) {
            float a0 = As[k][ty * 4 + 0], a1 = As[k][ty * 4 + 1];
            float a2 = As[k][ty * 4 + 2], a3 = As[k][ty * 4 + 3];
            float4 b = *(const float4*)&Bs[k][tx * 4];
            acc[0][0] += a0 * b.x; acc[0][1] += a0 * b.y; acc[0][2] += a0 * b.z; acc[0][3] += a0 * b.w;
            acc[1][0] += a1 * b.x; acc[1][1] += a1 * b.y; acc[1][2] += a1 * b.z; acc[1][3] += a1 * b.w;
            acc[2][0] += a2 * b.x; acc[2][1] += a2 * b.y; acc[2][2] += a2 * b.z; acc[2][3] += a2 * b.w;
            acc[3][0] += a3 * b.x; acc[3][1] += a3 * b.y; acc[3][2] += a3 * b.z; acc[3][3] += a3 * b.w;
        }
        __syncthreads();
    }
    // epilogue: bias + BN + leaky relu
    int c0 = n0 + tx * 4;
    float sc[4], sh[4];
#pragma unroll
    for (int j = 0; j < 4; j++) {
        int c = c0 + j;
        float s = gamma[c] * rsqrtf(var[c] + 1e-3f);
        sc[j] = s;
        sh[j] = beta[c] + (bd1[c] - mean[c]) * s;
    }
#pragma unroll
    for (int i = 0; i < 4; i++) {
        int row = row0 + ty * 4 + i;
#pragma unroll
        for (int j = 0; j < 4; j++) {
            float v = acc[i][j] * sc[j] + sh[j];
            g_act[(size_t)row * D_DENSE + c0 + j] = (v >= 0.f) ? v : 0.2f * v;
        }
    }
}

// ---------------- fused LSTM step: z = [x_t|h] @ Wc + bc, gate fusion in epilogue ----------------
// L=1: xin=g_act (cols t*16..), H=128;  L=2: xin=g_h1 output of this step, H=32.
template <int KX, int H, int L>
__global__ __launch_bounds__(256) void lstm_step_kernel(int t) {
    constexpr int K = KX + H;
    constexpr int N = 4 * H;
    const int p = t & 1;
    const float* xin;
    int xstride, xcol0;
    const float* hprev;
    float* cbuf;
    float* hout;
    const float* Wc;
    const float* bc;
    if (L == 1) {
        xin = g_act; xstride = D_DENSE; xcol0 = t * FEAT;
        hprev = g_h1[p]; cbuf = g_c1; hout = g_h1[p ^ 1];
        Wc = g_Wc1; bc = g_bc1;
    } else {
        xin = g_h1[p ^ 1]; xstride = H1; xcol0 = 0;
        hprev = g_h2[p]; cbuf = g_c2; hout = g_h2[p ^ 1];
        Wc = g_Wc2; bc = g_bc2;
    }

    __shared__ float As[16][65];
    __shared__ float Bs[16][64];
    const int tid = threadIdx.x;
    const int tx = tid & 15, ty = tid >> 4;
    const int row0 = blockIdx.x * 64, n0 = blockIdx.y * 64;
    float acc[4][4] = {};

    for (int kc = 0; kc < K / 16; kc++) {
        int kg0 = kc * 16;
        if (kg0 < KX) {
#pragma unroll
            for (int i = 0; i < 4; i++) {
                int li = tid + i * 256;
                int k = li & 15, r = li >> 4;
                As[k][r] = xin[(size_t)(row0 + r) * xstride + xcol0 + kg0 + k];
            }
        } else {
#pragma unroll
            for (int i = 0; i < 4; i++) {
                int li = tid + i * 256;
                int k = li & 15, r = li >> 4;
                As[k][r] = hprev[(size_t)(row0 + r) * H + (kg0 - KX) + k];
            }
        }
#pragma unroll
        for (int i = 0; i < 4; i++) {
            int li = tid + i * 256;
            int n = li & 63, k = li >> 6;
            Bs[k][n] = Wc[(size_t)(kg0 + k) * N + n0 + n];
        }
        __syncthreads();
#pragma unroll
        for (int k = 0; k < 16; k++) {
            float a0 = As[k][ty * 4 + 0], a1 = As[k][ty * 4 + 1];
            float a2 = As[k][ty * 4 + 2], a3 = As[k][ty * 4 + 3];
            float4 b = *(const float4*)&Bs[k][tx * 4];
            acc[0][0] += a0 * b.x; acc[0][1] += a0 * b.y; acc[0][2] += a0 * b.z; acc[0][3] += a0 * b.w;
            acc[1][0] += a1 * b.x; acc[1][1] += a1 * b.y; acc[1][2] += a1 * b.z; acc[1][3] += a1 * b.w;
            acc[2][0] += a2 * b.x; acc[2][1] += a2 * b.y; acc[2][2] += a2 * b.z; acc[2][3] += a2 * b.w;
            acc[3][0] += a3 * b.x; acc[3][1] += a3 * b.y; acc[3][2] += a3 * b.z; acc[3][3] += a3 * b.w;
        }
        __syncthreads();
    }

    // epilogue: columns tx*4..tx*4+3 are gates i,f,g,o of unit u
    int u = (n0 >> 2) + tx;
    float4 bb = *(const float4*)&bc[n0 + tx * 4];
#pragma unroll
    for (int i = 0; i < 4; i++) {
        int row = row0 + ty * 4 + i;
        float zi = acc[i][0] + bb.x;
        float zf = acc[i][1] + bb.y;
        float zg = acc[i][2] + bb.z;
        float zo = acc[i][3] + bb.w;
        float ig = 1.f / (1.f + expf(-zi));
        float fg = 1.f / (1.f + expf(-zf));
        float gg = tanhf(zg);
        float og = 1.f / (1.f + expf(-zo));
        size_t off = (size_t)row * H + u;
        float cn = fg * cbuf[off] + ig * gg;
        cbuf[off] = cn;
        hout[off] = og * tanhf(cn);
    }
}

// ---------------- Dense2 + softmax ----------------
__global__ __launch_bounds__(256) void dense2_softmax_kernel(
    const float* __restrict__ Wd2, const float* __restrict__ bd2, float* __restrict__ out) {
    __shared__ float Ws[H2 * NCLS];
    __shared__ float bs[NCLS];
    int tid = threadIdx.x;
    for (int i = tid; i < H2 * NCLS; i += blockDim.x) Ws[i] = Wd2[i];   // FIX: 320 > 256, need strided load
    if (tid < NCLS) bs[tid] = bd2[tid];
    __syncthreads();
    int row = blockIdx.x * blockDim.x + tid;
    const float* h = &g_h2[0][(size_t)row * H2];  // final step writes buffer 0 (t=15 -> out = (15&1)^1 = 0)
    float acc[NCLS];
#pragma unroll
    for (int j = 0; j < NCLS; j++) acc[j] = bs[j];
#pragma unroll
    for (int k = 0; k < H2; k++) {
        float xv = h[k];
#pragma unroll
        for (int j = 0; j < NCLS; j++) acc[j] += xv * Ws[k * NCLS + j];
    }
    float m = acc[0];
#pragma unroll
    for (int j = 1; j < NCLS; j++) m = fmaxf(m, acc[j]);
    float ssum = 0.f;
#pragma unroll
    for (int j = 0; j < NCLS; j++) { acc[j] = expf(acc[j] - m); ssum += acc[j]; }
    float inv = 1.f / ssum;
#pragma unroll
    for (int j = 0; j < NCLS; j++) out[(size_t)row * NCLS + j] = acc[j] * inv;
}

// ---------------- launch ----------------
extern "C" void kernel_launch(void* const* d_in, const int* in_sizes, int n_in,
                              void* d_out, int out_size) {
    const float* x        = (const float*)d_in[0];
    const float* W_d1     = (const float*)d_in[1];
    const float* b_d1     = (const float*)d_in[2];
    const float* bn_gamma = (const float*)d_in[3];
    const float* bn_beta  = (const float*)d_in[4];
    const float* bn_mean  = (const float*)d_in[5];
    const float* bn_var   = (const float*)d_in[6];
    const float* Wx1      = (const float*)d_in[7];
    const float* Wh1      = (const float*)d_in[8];
    const float* b1       = (const float*)d_in[9];
    const float* Wx2      = (const float*)d_in[10];
    const float* Wh2      = (const float*)d_in[11];
    const float* b2       = (const float*)d_in[12];
    const float* W_d2     = (const float*)d_in[13];
    const float* b_d2     = (const float*)d_in[14];
    float* out = (float*)d_out;

    repack_kernel<<<128, 256>>>(Wx1, Wh1, b1, Wx2, Wh2, b2);
    init_state_kernel<<<2048, 256>>>();
    {
        dim3 grid(BATCH / 64, D_DENSE / 64);
        dense1_kernel<<<grid, 256>>>(x, W_d1, b_d1, bn_gamma, bn_beta, bn_mean, bn_var);
    }
    for (int t = 0; t < TSTEPS; t++) {
        dim3 g1(BATCH / 64, 4 * H1 / 64);
        lstm_step_kernel<FEAT, H1, 1><<<g1, 256>>>(t);
        dim3 g2(BATCH / 64, 4 * H2 / 64);
        lstm_step_kernel<H1, H2, 2><<<g2, 256>>>(t);
    }
    dense2_softmax_kernel<<<BATCH / 256, 256>>>(W_d2, b_d2, out);
}